// round 2
// baseline (speedup 1.0000x reference)
#include <cuda_runtime.h>

#define NN 100000
#define NE 1000000
#define DD 64

// ---- scratch (device globals; no runtime allocation allowed) ----
__device__ int   g_deg_in[NN];
__device__ int   g_deg_out[NN];
__device__ int   g_row_ptr[NN + 1];
__device__ int   g_cursor[NN];
__device__ int   g_col[NE];
__device__ float g_y[NN * DD];   // GEMM output (pre-aggregation), reused both layers
__device__ float g_h[NN * DD];   // hidden activations after layer 1

// ---------------------------------------------------------------- CSR build
__global__ void k_zero_deg() {
    int i = blockIdx.x * blockDim.x + threadIdx.x;
    if (i < NN) { g_deg_in[i] = 0; g_deg_out[i] = 0; }
}

__global__ void k_hist(const int* __restrict__ src, const int* __restrict__ dst) {
    int i = blockIdx.x * blockDim.x + threadIdx.x;
    if (i < NE) {
        atomicAdd(&g_deg_out[src[i]], 1);
        atomicAdd(&g_deg_in[dst[i]], 1);
    }
}

// Single-block exclusive scan of deg_in -> row_ptr (N=100K, 1024 threads x ~98 elems)
__global__ void k_scan() {
    __shared__ int s[1024];
    const int t = threadIdx.x;
    const int per = (NN + 1023) / 1024;
    int start = t * per;
    int end = min(start + per, NN);
    int sum = 0;
    for (int i = start; i < end; i++) sum += g_deg_in[i];
    s[t] = sum;
    __syncthreads();
    for (int off = 1; off < 1024; off <<= 1) {
        int v = (t >= off) ? s[t - off] : 0;
        __syncthreads();
        s[t] += v;
        __syncthreads();
    }
    int run = (t > 0) ? s[t - 1] : 0;
    for (int i = start; i < end; i++) {
        g_row_ptr[i] = run;
        g_cursor[i]  = run;
        run += g_deg_in[i];
    }
    if (t == 1023) g_row_ptr[NN] = run;  // == NE
}

__global__ void k_scatter(const int* __restrict__ src, const int* __restrict__ dst) {
    int i = blockIdx.x * blockDim.x + threadIdx.x;
    if (i < NE) {
        int d = dst[i];
        int p = atomicAdd(&g_cursor[d], 1);
        g_col[p] = src[i];
    }
}

// ---------------------------------------------------------------- GEMM
// C[row,:] = (A[row,:] * rsqrt(max(deg_out[row],1))) @ W   (64x64 W)
// Block: 256 threads, 64 rows per block; thread tile 4x4.
__global__ void __launch_bounds__(256) k_gemm(const float* __restrict__ A,
                                              const float* __restrict__ W,
                                              float* __restrict__ C) {
    __shared__ float As[64][64];
    __shared__ float Ws[64][64];
    const int tid = threadIdx.x;
    const int block_row = blockIdx.x * 64;

    // load W (4096 floats) via float4
    {
        const float4* Wv  = (const float4*)W;
        float4*       Wsv = (float4*)Ws;
        #pragma unroll
        for (int i = 0; i < 4; i++) Wsv[tid + i * 256] = Wv[tid + i * 256];
    }
    // load A tile with fused row scaling
    {
        const int r  = tid >> 4;          // 0..15
        const int c4 = (tid & 15) * 4;    // 0..60 step 4
        #pragma unroll
        for (int rr = 0; rr < 4; rr++) {
            int lrow = rr * 16 + r;
            int row = block_row + lrow;
            float4 v = make_float4(0.f, 0.f, 0.f, 0.f);
            float nrm = 0.f;
            if (row < NN) {
                v = *(const float4*)&A[row * DD + c4];
                int dg = g_deg_out[row];
                nrm = rsqrtf((float)(dg > 1 ? dg : 1));
            }
            v.x *= nrm; v.y *= nrm; v.z *= nrm; v.w *= nrm;
            *(float4*)&As[lrow][c4] = v;
        }
    }
    __syncthreads();

    const int ty4 = (tid >> 4) * 4;   // row base 0..60
    const int tx4 = (tid & 15) * 4;   // col base 0..60
    float acc[4][4] = {};
    #pragma unroll 16
    for (int k = 0; k < 64; k++) {
        float a0 = As[ty4 + 0][k];
        float a1 = As[ty4 + 1][k];
        float a2 = As[ty4 + 2][k];
        float a3 = As[ty4 + 3][k];
        float4 w = *(const float4*)&Ws[k][tx4];
        acc[0][0] += a0 * w.x; acc[0][1] += a0 * w.y; acc[0][2] += a0 * w.z; acc[0][3] += a0 * w.w;
        acc[1][0] += a1 * w.x; acc[1][1] += a1 * w.y; acc[1][2] += a1 * w.z; acc[1][3] += a1 * w.w;
        acc[2][0] += a2 * w.x; acc[2][1] += a2 * w.y; acc[2][2] += a2 * w.z; acc[2][3] += a2 * w.w;
        acc[3][0] += a3 * w.x; acc[3][1] += a3 * w.y; acc[3][2] += a3 * w.z; acc[3][3] += a3 * w.w;
    }
    #pragma unroll
    for (int i = 0; i < 4; i++) {
        int row = block_row + ty4 + i;
        if (row < NN)
            *(float4*)&C[row * DD + tx4] =
                make_float4(acc[i][0], acc[i][1], acc[i][2], acc[i][3]);
    }
}

// ---------------------------------------------------------------- aggregate
// out[i,:] = act( norm_in[i] * sum_{e in CSR row i} y[col[e],:] + b )
// One warp per node, float2 per lane (256B coalesced row reads, L2-resident).
// 8-deep edge unroll for MLP (16 independent LDG.64 in flight per lane batch).
template <bool RELU>
__global__ void __launch_bounds__(256) k_agg(const float* __restrict__ y,
                                             const float* __restrict__ b,
                                             float* __restrict__ out) {
    const int warp = (blockIdx.x * blockDim.x + threadIdx.x) >> 5;
    const int lane = threadIdx.x & 31;
    if (warp >= NN) return;
    const int beg = g_row_ptr[warp];
    const int end = g_row_ptr[warp + 1];
    const int off = lane * 2;

    float ax = 0.f, ay = 0.f;
    int k = beg;
    for (; k + 8 <= end; k += 8) {
        int s0 = __ldg(&g_col[k + 0]);
        int s1 = __ldg(&g_col[k + 1]);
        int s2 = __ldg(&g_col[k + 2]);
        int s3 = __ldg(&g_col[k + 3]);
        int s4 = __ldg(&g_col[k + 4]);
        int s5 = __ldg(&g_col[k + 5]);
        int s6 = __ldg(&g_col[k + 6]);
        int s7 = __ldg(&g_col[k + 7]);
        float2 v0 = *(const float2*)&y[s0 * DD + off];
        float2 v1 = *(const float2*)&y[s1 * DD + off];
        float2 v2 = *(const float2*)&y[s2 * DD + off];
        float2 v3 = *(const float2*)&y[s3 * DD + off];
        float2 v4 = *(const float2*)&y[s4 * DD + off];
        float2 v5 = *(const float2*)&y[s5 * DD + off];
        float2 v6 = *(const float2*)&y[s6 * DD + off];
        float2 v7 = *(const float2*)&y[s7 * DD + off];
        ax += ((v0.x + v1.x) + (v2.x + v3.x)) + ((v4.x + v5.x) + (v6.x + v7.x));
        ay += ((v0.y + v1.y) + (v2.y + v3.y)) + ((v4.y + v5.y) + (v6.y + v7.y));
    }
    for (; k < end; k++) {
        int s = __ldg(&g_col[k]);
        float2 v = *(const float2*)&y[s * DD + off];
        ax += v.x; ay += v.y;
    }
    int dg = g_deg_in[warp];
    float nrm = rsqrtf((float)(dg > 1 ? dg : 1));
    float2 bb = *(const float2*)&b[off];
    float ox = ax * nrm + bb.x;
    float oy = ay * nrm + bb.y;
    if (RELU) { ox = fmaxf(ox, 0.f); oy = fmaxf(oy, 0.f); }
    *(float2*)&out[warp * DD + off] = make_float2(ox, oy);
}

// ---------------------------------------------------------------- launch
extern "C" void kernel_launch(void* const* d_in, const int* in_sizes, int n_in,
                              void* d_out, int out_size) {
    const int*   src = (const int*)d_in[0];
    const int*   dst = (const int*)d_in[1];
    const float* x   = (const float*)d_in[2];
    const float* W1  = (const float*)d_in[3];
    const float* b1  = (const float*)d_in[4];
    const float* W2  = (const float*)d_in[5];
    const float* b2  = (const float*)d_in[6];
    float*       out = (float*)d_out;

    float *y, *h;
    cudaGetSymbolAddress((void**)&y, g_y);
    cudaGetSymbolAddress((void**)&h, g_h);

    // CSR build (per-call; deterministic work)
    k_zero_deg<<<(NN + 255) / 256, 256>>>();
    k_hist<<<(NE + 255) / 256, 256>>>(src, dst);
    k_scan<<<1, 1024>>>();
    k_scatter<<<(NE + 255) / 256, 256>>>(src, dst);

    const int gemm_blocks = (NN + 63) / 64;
    const int agg_blocks  = (NN * 32 + 255) / 256;  // warp per node, 8 warps/block

    // Layer 1: y = (x * norm_out) @ W1 ; h = relu(S y * norm_in + b1)
    k_gemm<<<gemm_blocks, 256>>>(x, W1, y);
    k_agg<true><<<agg_blocks, 256>>>(y, b1, h);

    // Layer 2: y = (h * norm_out) @ W2 ; out = S y * norm_in + b2
    k_gemm<<<gemm_blocks, 256>>>(h, W2, y);
    k_agg<false><<<agg_blocks, 256>>>(y, b2, out);
}

// round 3
// speedup vs baseline: 2.2424x; 2.2424x over previous
#include <cuda_runtime.h>

#define NN 100000
#define NE 1000000
#define DD 64
#define NB ((NN + 255) / 256)   // 391 blocks of 256 for scan

// ---- scratch (device globals; no runtime allocation allowed) ----
__device__ int   g_deg_in[NN];
__device__ int   g_deg_out[NN];
__device__ int   g_row_ptr[NN + 1];
__device__ int   g_cursor[NN];
__device__ int   g_col[NE];
__device__ int   g_bsum[NB];
__device__ float g_y[NN * DD];   // GEMM output (pre-aggregation), reused both layers
__device__ float g_h[NN * DD];   // hidden activations after layer 1

// ---------------------------------------------------------------- CSR build
__global__ void k_hist(const int* __restrict__ src, const int* __restrict__ dst) {
    int i = blockIdx.x * blockDim.x + threadIdx.x;
    if (i < NE) {
        atomicAdd(&g_deg_out[src[i]], 1);
        atomicAdd(&g_deg_in[dst[i]], 1);
    }
}

// Per-block partial sums of deg_in (256 elems per block)
__global__ void __launch_bounds__(256) k_bsum() {
    int i = blockIdx.x * 256 + threadIdx.x;
    int v = (i < NN) ? g_deg_in[i] : 0;
    #pragma unroll
    for (int o = 16; o; o >>= 1) v += __shfl_down_sync(0xffffffffu, v, o);
    __shared__ int ws[8];
    if ((threadIdx.x & 31) == 0) ws[threadIdx.x >> 5] = v;
    __syncthreads();
    if (threadIdx.x == 0) {
        int s = 0;
        #pragma unroll
        for (int w = 0; w < 8; w++) s += ws[w];
        g_bsum[blockIdx.x] = s;
    }
}

// Each block: offset = sum(bsum[0..b)), then block-local exclusive scan of its
// 256 degrees -> row_ptr + cursor.
__global__ void __launch_bounds__(256) k_rowptr() {
    const int b = blockIdx.x;
    const int t = threadIdx.x;
    const int lane = t & 31, w = t >> 5;

    // global offset: sum of preceding block sums
    int acc = 0;
    for (int j = t; j < b; j += 256) acc += g_bsum[j];
    #pragma unroll
    for (int o = 16; o; o >>= 1) acc += __shfl_down_sync(0xffffffffu, acc, o);
    __shared__ int red[8];
    if (lane == 0) red[w] = acc;
    __syncthreads();
    __shared__ int s_off;
    if (t == 0) {
        int s = 0;
        #pragma unroll
        for (int j = 0; j < 8; j++) s += red[j];
        s_off = s;
    }
    __syncthreads();

    const int i = b * 256 + t;
    int d = (i < NN) ? g_deg_in[i] : 0;

    // block exclusive scan of d
    int inc = d;
    #pragma unroll
    for (int o = 1; o < 32; o <<= 1) {
        int u = __shfl_up_sync(0xffffffffu, inc, o);
        if (lane >= o) inc += u;
    }
    __shared__ int wsum[8];
    if (lane == 31) wsum[w] = inc;
    __syncthreads();
    if (t == 0) {
        int r = 0;
        #pragma unroll
        for (int j = 0; j < 8; j++) { int tmp = wsum[j]; wsum[j] = r; r += tmp; }
    }
    __syncthreads();
    int exc = s_off + wsum[w] + inc - d;
    if (i < NN) { g_row_ptr[i] = exc; g_cursor[i] = exc; }
    if (i == NN - 1) g_row_ptr[NN] = exc + d;
}

__global__ void k_scatter(const int* __restrict__ src, const int* __restrict__ dst) {
    int i = blockIdx.x * blockDim.x + threadIdx.x;
    if (i < NE) {
        int d = dst[i];
        int p = atomicAdd(&g_cursor[d], 1);
        g_col[p] = src[i];
    }
}

// ---------------------------------------------------------------- GEMM
// C[row,:] = (A[row,:] * rsqrt(max(deg_out[row],1))) @ W   (64x64 W)
__global__ void __launch_bounds__(256) k_gemm(const float* __restrict__ A,
                                              const float* __restrict__ W,
                                              float* __restrict__ C) {
    __shared__ float As[64][64];
    __shared__ float Ws[64][64];
    const int tid = threadIdx.x;
    const int block_row = blockIdx.x * 64;

    {
        const float4* Wv  = (const float4*)W;
        float4*       Wsv = (float4*)Ws;
        #pragma unroll
        for (int i = 0; i < 4; i++) Wsv[tid + i * 256] = Wv[tid + i * 256];
    }
    {
        const int r  = tid >> 4;
        const int c4 = (tid & 15) * 4;
        #pragma unroll
        for (int rr = 0; rr < 4; rr++) {
            int lrow = rr * 16 + r;
            int row = block_row + lrow;
            float4 v = make_float4(0.f, 0.f, 0.f, 0.f);
            float nrm = 0.f;
            if (row < NN) {
                v = *(const float4*)&A[row * DD + c4];
                int dg = g_deg_out[row];
                nrm = rsqrtf((float)(dg > 1 ? dg : 1));
            }
            v.x *= nrm; v.y *= nrm; v.z *= nrm; v.w *= nrm;
            *(float4*)&As[lrow][c4] = v;
        }
    }
    __syncthreads();

    const int ty4 = (tid >> 4) * 4;
    const int tx4 = (tid & 15) * 4;
    float acc[4][4] = {};
    #pragma unroll 16
    for (int k = 0; k < 64; k++) {
        float a0 = As[ty4 + 0][k];
        float a1 = As[ty4 + 1][k];
        float a2 = As[ty4 + 2][k];
        float a3 = As[ty4 + 3][k];
        float4 w = *(const float4*)&Ws[k][tx4];
        acc[0][0] += a0 * w.x; acc[0][1] += a0 * w.y; acc[0][2] += a0 * w.z; acc[0][3] += a0 * w.w;
        acc[1][0] += a1 * w.x; acc[1][1] += a1 * w.y; acc[1][2] += a1 * w.z; acc[1][3] += a1 * w.w;
        acc[2][0] += a2 * w.x; acc[2][1] += a2 * w.y; acc[2][2] += a2 * w.z; acc[2][3] += a2 * w.w;
        acc[3][0] += a3 * w.x; acc[3][1] += a3 * w.y; acc[3][2] += a3 * w.z; acc[3][3] += a3 * w.w;
    }
    #pragma unroll
    for (int i = 0; i < 4; i++) {
        int row = block_row + ty4 + i;
        if (row < NN)
            *(float4*)&C[row * DD + tx4] =
                make_float4(acc[i][0], acc[i][1], acc[i][2], acc[i][3]);
    }
}

// ---------------------------------------------------------------- aggregate
// out[i,:] = act( norm_in[i] * sum_{e in CSR row i} y[col[e],:] + b )
// 16 lanes per node (float4 each -> 256B row); fully-predicated unroll-8:
// no serial remainder, 8 idx + 8 row loads always independently in flight.
template <bool RELU>
__global__ void __launch_bounds__(256) k_agg(const float* __restrict__ y,
                                             const float* __restrict__ b,
                                             float* __restrict__ out) {
    const int gtid = blockIdx.x * blockDim.x + threadIdx.x;
    const int node = gtid >> 4;
    const int lane = threadIdx.x & 15;
    if (node >= NN) return;
    const int beg = g_row_ptr[node];
    const int end = g_row_ptr[node + 1];
    const int off = lane * 4;

    float ax = 0.f, ay = 0.f, az = 0.f, aw = 0.f;
    for (int k = beg; k < end; k += 8) {
        int   idx[8];
        #pragma unroll
        for (int j = 0; j < 8; j++) {
            int kk = k + j;
            idx[j] = __ldg(&g_col[kk < end ? kk : beg]);
        }
        float4 v[8];
        #pragma unroll
        for (int j = 0; j < 8; j++)
            v[j] = *(const float4*)&y[idx[j] * DD + off];
        #pragma unroll
        for (int j = 0; j < 8; j++) {
            if (k + j < end) { ax += v[j].x; ay += v[j].y; az += v[j].z; aw += v[j].w; }
        }
    }

    int dg = g_deg_in[node];
    float nrm = rsqrtf((float)(dg > 1 ? dg : 1));
    float4 bb = *(const float4*)&b[off];
    float ox = ax * nrm + bb.x;
    float oy = ay * nrm + bb.y;
    float oz = az * nrm + bb.z;
    float ow = aw * nrm + bb.w;
    if (RELU) {
        ox = fmaxf(ox, 0.f); oy = fmaxf(oy, 0.f);
        oz = fmaxf(oz, 0.f); ow = fmaxf(ow, 0.f);
    }
    *(float4*)&out[node * DD + off] = make_float4(ox, oy, oz, ow);
}

// ---------------------------------------------------------------- launch
extern "C" void kernel_launch(void* const* d_in, const int* in_sizes, int n_in,
                              void* d_out, int out_size) {
    const int*   src = (const int*)d_in[0];
    const int*   dst = (const int*)d_in[1];
    const float* x   = (const float*)d_in[2];
    const float* W1  = (const float*)d_in[3];
    const float* b1  = (const float*)d_in[4];
    const float* W2  = (const float*)d_in[5];
    const float* b2  = (const float*)d_in[6];
    float*       out = (float*)d_out;

    float *y, *h;
    int *deg_in, *deg_out;
    cudaGetSymbolAddress((void**)&y, g_y);
    cudaGetSymbolAddress((void**)&h, g_h);
    cudaGetSymbolAddress((void**)&deg_in, g_deg_in);
    cudaGetSymbolAddress((void**)&deg_out, g_deg_out);

    // CSR build (per-call; deterministic work)
    cudaMemsetAsync(deg_in, 0, NN * sizeof(int));
    cudaMemsetAsync(deg_out, 0, NN * sizeof(int));
    k_hist<<<(NE + 255) / 256, 256>>>(src, dst);
    k_bsum<<<NB, 256>>>();
    k_rowptr<<<NB, 256>>>();
    k_scatter<<<(NE + 255) / 256, 256>>>(src, dst);

    const int gemm_blocks = (NN + 63) / 64;
    const int agg_blocks  = (NN * 16 + 255) / 256;  // 16 threads per node

    // Layer 1: y = (x * norm_out) @ W1 ; h = relu(S y * norm_in + b1)
    k_gemm<<<gemm_blocks, 256>>>(x, W1, y);
    k_agg<true><<<agg_blocks, 256>>>(y, b1, h);

    // Layer 2: y = (h * norm_out) @ W2 ; out = S y * norm_in + b2
    k_gemm<<<gemm_blocks, 256>>>(h, W2, y);
    k_agg<false><<<agg_blocks, 256>>>(y, b2, out);
}